// round 2
// baseline (speedup 1.0000x reference)
#include <cuda_runtime.h>

#define NN 100000
#define EE 3200000

// ---------------- persistent device scratch (no allocations allowed) ----------------
__device__ int2   g_edges[EE];
__device__ float  g_norm[EE];
__device__ int    g_deg[NN];
__device__ float  g_dis[NN];
__device__ float4 g_hA[NN * 4];    // layer-1 transformed features (16 f32 / node)
__device__ float4 g_aggA[NN * 4];  // layer-1 aggregation
__device__ float4 g_hB[NN * 4];    // layer-2 transformed
__device__ float4 g_aggB[NN * 4];  // layer-2 aggregation
__device__ float2 g_h3[NN];        // layer-3 transformed (2 f32 / node)
__device__ float2 g_agg3[NN];      // layer-3 aggregation

// ---------------- vector reductions (sm_90+) ----------------
__device__ __forceinline__ void red_add_v4(float4* addr, float4 v) {
    asm volatile("red.global.add.v4.f32 [%0], {%1,%2,%3,%4};"
                 :: "l"(addr), "f"(v.x), "f"(v.y), "f"(v.z), "f"(v.w)
                 : "memory");
}
__device__ __forceinline__ void red_add_v2(float2* addr, float2 v) {
    asm volatile("red.global.add.v2.f32 [%0], {%1,%2};"
                 :: "l"(addr), "f"(v.x), "f"(v.y)
                 : "memory");
}

// ---------------- prep kernels ----------------
__global__ void zero_deg(int n) {
    int i = blockIdx.x * 256 + threadIdx.x;
    if (i < n) g_deg[i] = 0;
}

// edge_index is int32 (JAX x64 disabled downcasts jnp.int64 -> int32)
__global__ void prep_edges(const int* __restrict__ ei, int e) {
    int i = blockIdx.x * 256 + threadIdx.x;
    if (i >= e) return;
    int s = ei[i];
    int d = ei[e + i];
    g_edges[i] = make_int2(s, d);
    atomicAdd(&g_deg[d], 1);
}

__global__ void compute_dis(int n) {
    int i = blockIdx.x * 256 + threadIdx.x;
    if (i < n) g_dis[i] = rsqrtf((float)(g_deg[i] + 1));  // +1 self-loop
}

// ---------------- layer 1 transform: h = x @ W1 ; agg = h * dis^2 (self-loop init) ----------------
// 128 threads / block, 8 nodes / block, smem-staged x tile + transposed W1.
__global__ void gemm_in(const float4* __restrict__ x4, const float* __restrict__ W1, int n) {
    __shared__ float xs[8 * 132];    // 8 rows of 128, padded to 132 (bank spread)
    __shared__ float wt[16 * 132];   // transposed W1: [f][k], padded row 132

    int tid = threadIdx.x;
    // stage W1 transposed: wt[f][k] = W1[k*16 + f]
    for (int idx = tid; idx < 2048; idx += 128) {
        int f = idx >> 7, k = idx & 127;
        wt[f * 132 + k] = W1[k * 16 + f];
    }
    int nb = blockIdx.x * 8;
    // stage 8 x-rows, coalesced float4
    for (int idx = tid; idx < 256; idx += 128) {
        int r = idx >> 5, c = idx & 31;
        int node = nb + r;
        float4 v = (node < n) ? x4[(size_t)node * 32 + c] : make_float4(0.f, 0.f, 0.f, 0.f);
        ((float4*)(xs + r * 132))[c] = v;
    }
    __syncthreads();

    int f = tid & 15, nd = tid >> 4;
    const float4* xr = (const float4*)(xs + nd * 132);
    const float4* wr = (const float4*)(wt + f * 132);
    float acc = 0.f;
#pragma unroll
    for (int kk = 0; kk < 32; kk++) {
        float4 a = xr[kk], b = wr[kk];
        acc += a.x * b.x + a.y * b.y + a.z * b.z + a.w * b.w;
    }
    int node = nb + nd;
    if (node < n) {
        float s = g_dis[node];
        ((float*)g_hA)[node * 16 + f]   = acc;
        ((float*)g_aggA)[node * 16 + f] = acc * s * s;
    }
}

// ---------------- edge pass 1 (also materializes per-edge norm) ----------------
__global__ void edge_pass_a(int e) {
    int i = blockIdx.x * 256 + threadIdx.x;
    if (i >= e) return;
    int2 ed = g_edges[i];
    float nrm = __ldg(&g_dis[ed.x]) * __ldg(&g_dis[ed.y]);
    g_norm[i] = nrm;
    const float4* hp = g_hA + ed.x * 4;
    float4 a = hp[0], b = hp[1], c = hp[2], d = hp[3];
    a.x *= nrm; a.y *= nrm; a.z *= nrm; a.w *= nrm;
    b.x *= nrm; b.y *= nrm; b.z *= nrm; b.w *= nrm;
    c.x *= nrm; c.y *= nrm; c.z *= nrm; c.w *= nrm;
    d.x *= nrm; d.y *= nrm; d.z *= nrm; d.w *= nrm;
    float4* ap = g_aggA + ed.y * 4;
    red_add_v4(ap + 0, a);
    red_add_v4(ap + 1, b);
    red_add_v4(ap + 2, c);
    red_add_v4(ap + 3, d);
}

// ---------------- layer 2 transform: z = relu(aggA + b1); hB = z @ W2; aggB = hB * dis^2 ----------------
__global__ void transform_mid(const float* __restrict__ bias, const float4* __restrict__ W, int n) {
    __shared__ float4 Ws[64];   // 16x16 as float4 rows
    __shared__ float  bs[16];
    int tid = threadIdx.x;
    if (tid < 64) Ws[tid] = W[tid];
    if (tid < 16) bs[tid] = bias[tid];
    __syncthreads();
    int i = blockIdx.x * 256 + tid;
    if (i >= n) return;

    float z[16];
#pragma unroll
    for (int q = 0; q < 4; q++) {
        float4 v = g_aggA[i * 4 + q];
        z[q * 4 + 0] = fmaxf(v.x + bs[q * 4 + 0], 0.f);
        z[q * 4 + 1] = fmaxf(v.y + bs[q * 4 + 1], 0.f);
        z[q * 4 + 2] = fmaxf(v.z + bs[q * 4 + 2], 0.f);
        z[q * 4 + 3] = fmaxf(v.w + bs[q * 4 + 3], 0.f);
    }
    float4 o0 = make_float4(0.f,0.f,0.f,0.f), o1 = o0, o2 = o0, o3 = o0;
#pragma unroll
    for (int j = 0; j < 16; j++) {
        float zj = z[j];
        float4 w0 = Ws[j * 4 + 0], w1 = Ws[j * 4 + 1], w2 = Ws[j * 4 + 2], w3 = Ws[j * 4 + 3];
        o0.x += zj * w0.x; o0.y += zj * w0.y; o0.z += zj * w0.z; o0.w += zj * w0.w;
        o1.x += zj * w1.x; o1.y += zj * w1.y; o1.z += zj * w1.z; o1.w += zj * w1.w;
        o2.x += zj * w2.x; o2.y += zj * w2.y; o2.z += zj * w2.z; o2.w += zj * w2.w;
        o3.x += zj * w3.x; o3.y += zj * w3.y; o3.z += zj * w3.z; o3.w += zj * w3.w;
    }
    float s = g_dis[i], sl = s * s;
    g_hB[i * 4 + 0] = o0; g_hB[i * 4 + 1] = o1; g_hB[i * 4 + 2] = o2; g_hB[i * 4 + 3] = o3;
    float4 p0 = make_float4(o0.x*sl, o0.y*sl, o0.z*sl, o0.w*sl);
    float4 p1 = make_float4(o1.x*sl, o1.y*sl, o1.z*sl, o1.w*sl);
    float4 p2 = make_float4(o2.x*sl, o2.y*sl, o2.z*sl, o2.w*sl);
    float4 p3 = make_float4(o3.x*sl, o3.y*sl, o3.z*sl, o3.w*sl);
    g_aggB[i * 4 + 0] = p0; g_aggB[i * 4 + 1] = p1; g_aggB[i * 4 + 2] = p2; g_aggB[i * 4 + 3] = p3;
}

// ---------------- edge pass 2 (reuses cached norm) ----------------
__global__ void edge_pass_b(int e) {
    int i = blockIdx.x * 256 + threadIdx.x;
    if (i >= e) return;
    int2 ed = g_edges[i];
    float nrm = g_norm[i];
    const float4* hp = g_hB + ed.x * 4;
    float4 a = hp[0], b = hp[1], c = hp[2], d = hp[3];
    a.x *= nrm; a.y *= nrm; a.z *= nrm; a.w *= nrm;
    b.x *= nrm; b.y *= nrm; b.z *= nrm; b.w *= nrm;
    c.x *= nrm; c.y *= nrm; c.z *= nrm; c.w *= nrm;
    d.x *= nrm; d.y *= nrm; d.z *= nrm; d.w *= nrm;
    float4* ap = g_aggB + ed.y * 4;
    red_add_v4(ap + 0, a);
    red_add_v4(ap + 1, b);
    red_add_v4(ap + 2, c);
    red_add_v4(ap + 3, d);
}

// ---------------- layer 3 transform: z = relu(aggB + b2); h3 = z @ W3 (16->2); agg3 = h3 * dis^2 ----------------
__global__ void transform_last(const float* __restrict__ bias, const float* __restrict__ W3, int n) {
    __shared__ float Ws[32];   // 16x2
    __shared__ float bs[16];
    int tid = threadIdx.x;
    if (tid < 32) Ws[tid] = W3[tid];
    if (tid < 16) bs[tid] = bias[tid];
    __syncthreads();
    int i = blockIdx.x * 256 + tid;
    if (i >= n) return;

    float z[16];
#pragma unroll
    for (int q = 0; q < 4; q++) {
        float4 v = g_aggB[i * 4 + q];
        z[q * 4 + 0] = fmaxf(v.x + bs[q * 4 + 0], 0.f);
        z[q * 4 + 1] = fmaxf(v.y + bs[q * 4 + 1], 0.f);
        z[q * 4 + 2] = fmaxf(v.z + bs[q * 4 + 2], 0.f);
        z[q * 4 + 3] = fmaxf(v.w + bs[q * 4 + 3], 0.f);
    }
    float o0 = 0.f, o1 = 0.f;
#pragma unroll
    for (int j = 0; j < 16; j++) {
        o0 += z[j] * Ws[j * 2 + 0];
        o1 += z[j] * Ws[j * 2 + 1];
    }
    float s = g_dis[i], sl = s * s;
    g_h3[i]   = make_float2(o0, o1);
    g_agg3[i] = make_float2(o0 * sl, o1 * sl);
}

// ---------------- edge pass 3 (2-wide) ----------------
__global__ void edge_pass_c(int e) {
    int i = blockIdx.x * 256 + threadIdx.x;
    if (i >= e) return;
    int2 ed = g_edges[i];
    float nrm = g_norm[i];
    float2 v = g_h3[ed.x];
    red_add_v2(&g_agg3[ed.y], make_float2(v.x * nrm, v.y * nrm));
}

// ---------------- final: log_softmax(agg3 + b3) ----------------
__global__ void logsoftmax_out(const float* __restrict__ b3, float* __restrict__ out, int n) {
    int i = blockIdx.x * 256 + threadIdx.x;
    if (i >= n) return;
    float2 a = g_agg3[i];
    float a0 = a.x + b3[0];
    float a1 = a.y + b3[1];
    float m  = fmaxf(a0, a1);
    float lse = m + logf(expf(a0 - m) + expf(a1 - m));
    out[i * 2 + 0] = a0 - lse;
    out[i * 2 + 1] = a1 - lse;
}

// ---------------- launch ----------------
extern "C" void kernel_launch(void* const* d_in, const int* in_sizes, int n_in,
                              void* d_out, int out_size) {
    const float* x  = (const float*)d_in[0];
    const int*   ei = (const int*)d_in[1];     // int32 node ids (2 x E)
    const float* W1 = (const float*)d_in[2];
    const float* b1 = (const float*)d_in[3];
    const float* W2 = (const float*)d_in[4];
    const float* b2 = (const float*)d_in[5];
    const float* W3 = (const float*)d_in[6];
    const float* b3 = (const float*)d_in[7];
    float* out = (float*)d_out;

    int n = in_sizes[0] / 128;   // 100000
    int e = in_sizes[1] / 2;     // 3200000

    int nb = (n + 255) / 256;
    int ebk = (e + 255) / 256;

    zero_deg<<<nb, 256>>>(n);
    prep_edges<<<ebk, 256>>>(ei, e);
    compute_dis<<<nb, 256>>>(n);

    gemm_in<<<(n + 7) / 8, 128>>>((const float4*)x, W1, n);
    edge_pass_a<<<ebk, 256>>>(e);

    transform_mid<<<nb, 256>>>(b1, (const float4*)W2, n);
    edge_pass_b<<<ebk, 256>>>(e);

    transform_last<<<nb, 256>>>(b2, W3, n);
    edge_pass_c<<<ebk, 256>>>(e);

    logsoftmax_out<<<nb, 256>>>(b3, out, n);
}

// round 3
// speedup vs baseline: 1.5798x; 1.5798x over previous
#include <cuda_runtime.h>

#define NN 100000
#define EE 3200000

// ---------------- persistent device scratch (no allocations allowed) ----------------
__device__ int2   g_edges[EE];
__device__ float  g_norm[EE];
__device__ int    g_deg[NN];
__device__ float  g_dis[NN];
__device__ float4 g_hA[NN * 4];    // layer-1 transformed features (16 f32 / node)
__device__ float4 g_aggA[NN * 4];  // layer-1 aggregation
__device__ float4 g_hB[NN * 4];    // layer-2 transformed
__device__ float4 g_aggB[NN * 4];  // layer-2 aggregation
__device__ float2 g_h3[NN];        // layer-3 transformed (2 f32 / node)
__device__ float2 g_agg3[NN];      // layer-3 aggregation

// ---------------- vector reductions (sm_90+) ----------------
__device__ __forceinline__ void red_add_v4(float4* addr, float4 v) {
    asm volatile("red.global.add.v4.f32 [%0], {%1,%2,%3,%4};"
                 :: "l"(addr), "f"(v.x), "f"(v.y), "f"(v.z), "f"(v.w)
                 : "memory");
}
__device__ __forceinline__ void red_add_v2(float2* addr, float2 v) {
    asm volatile("red.global.add.v2.f32 [%0], {%1,%2};"
                 :: "l"(addr), "f"(v.x), "f"(v.y)
                 : "memory");
}

// ---------------- prep kernels ----------------
__global__ void zero_deg(int n) {
    int i = blockIdx.x * 256 + threadIdx.x;
    if (i < n) g_deg[i] = 0;
}

// edge_index is int32 (JAX x64 disabled downcasts jnp.int64 -> int32)
__global__ void prep_edges(const int* __restrict__ ei, int e) {
    int i = blockIdx.x * 256 + threadIdx.x;
    if (i >= e) return;
    int s = ei[i];
    int d = ei[e + i];
    g_edges[i] = make_int2(s, d);
    atomicAdd(&g_deg[d], 1);
}

__global__ void compute_dis(int n) {
    int i = blockIdx.x * 256 + threadIdx.x;
    if (i < n) g_dis[i] = rsqrtf((float)(g_deg[i] + 1));  // +1 self-loop
}

// ---------------- layer 1 transform: h = x @ W1 ; agg = h * dis^2 (self-loop init) ----
// One node per thread; 16 register accumulators; W1 staged in smem and read via
// warp-uniform broadcast LDS.128 (1 wavefront per instruction); x rows read
// directly from global as float4.
__global__ void gemm_in(const float4* __restrict__ x4, const float4* __restrict__ W1v, int n) {
    __shared__ float4 wt[512];   // W1 [128][16] row-major: wt[k*4 + j] = cols 4j..4j+3 of row k
    int tid = threadIdx.x;
#pragma unroll
    for (int idx = tid; idx < 512; idx += 256) wt[idx] = W1v[idx];
    __syncthreads();

    int node = blockIdx.x * 256 + tid;
    if (node >= n) return;

    float acc[16];
#pragma unroll
    for (int j = 0; j < 16; j++) acc[j] = 0.f;

    const float4* xr = x4 + (size_t)node * 32;
#pragma unroll 4
    for (int kk = 0; kk < 32; kk++) {
        float4 xv = xr[kk];
        int kb = kk * 16;           // 4 k-rows of W, 4 float4 each
#pragma unroll
        for (int j = 0; j < 4; j++) {
            float xs_ = (j == 0) ? xv.x : (j == 1) ? xv.y : (j == 2) ? xv.z : xv.w;
            float4 w0 = wt[kb + j * 4 + 0];
            float4 w1 = wt[kb + j * 4 + 1];
            float4 w2 = wt[kb + j * 4 + 2];
            float4 w3 = wt[kb + j * 4 + 3];
            acc[0]  += xs_ * w0.x; acc[1]  += xs_ * w0.y; acc[2]  += xs_ * w0.z; acc[3]  += xs_ * w0.w;
            acc[4]  += xs_ * w1.x; acc[5]  += xs_ * w1.y; acc[6]  += xs_ * w1.z; acc[7]  += xs_ * w1.w;
            acc[8]  += xs_ * w2.x; acc[9]  += xs_ * w2.y; acc[10] += xs_ * w2.z; acc[11] += xs_ * w2.w;
            acc[12] += xs_ * w3.x; acc[13] += xs_ * w3.y; acc[14] += xs_ * w3.z; acc[15] += xs_ * w3.w;
        }
    }

    float s = g_dis[node], sl = s * s;
#pragma unroll
    for (int q = 0; q < 4; q++) {
        float4 h = make_float4(acc[q*4+0], acc[q*4+1], acc[q*4+2], acc[q*4+3]);
        g_hA[node * 4 + q] = h;
        g_aggA[node * 4 + q] = make_float4(h.x * sl, h.y * sl, h.z * sl, h.w * sl);
    }
}

// ---------------- edge pass 1: quad-cooperative (4 lanes per edge) ----------------
__global__ void edge_pass_a(int e) {
    int t = blockIdx.x * 256 + threadIdx.x;
    int edge = t >> 2, q = t & 3;
    if (edge >= e) return;
    int2 ed = g_edges[edge];
    float nrm = __ldg(&g_dis[ed.x]) * __ldg(&g_dis[ed.y]);
    if (q == 0) g_norm[edge] = nrm;
    float4 v = g_hA[ed.x * 4 + q];
    v.x *= nrm; v.y *= nrm; v.z *= nrm; v.w *= nrm;
    red_add_v4(&g_aggA[ed.y * 4 + q], v);
}

// ---------------- layer 2 transform: z = relu(aggA + b1); hB = z @ W2; aggB = hB * dis^2 ----
__global__ void transform_mid(const float* __restrict__ bias, const float4* __restrict__ W, int n) {
    __shared__ float4 Ws[64];   // 16x16 as float4 rows
    __shared__ float  bs[16];
    int tid = threadIdx.x;
    if (tid < 64) Ws[tid] = W[tid];
    if (tid < 16) bs[tid] = bias[tid];
    __syncthreads();
    int i = blockIdx.x * 256 + tid;
    if (i >= n) return;

    float z[16];
#pragma unroll
    for (int q = 0; q < 4; q++) {
        float4 v = g_aggA[i * 4 + q];
        z[q * 4 + 0] = fmaxf(v.x + bs[q * 4 + 0], 0.f);
        z[q * 4 + 1] = fmaxf(v.y + bs[q * 4 + 1], 0.f);
        z[q * 4 + 2] = fmaxf(v.z + bs[q * 4 + 2], 0.f);
        z[q * 4 + 3] = fmaxf(v.w + bs[q * 4 + 3], 0.f);
    }
    float4 o0 = make_float4(0.f,0.f,0.f,0.f), o1 = o0, o2 = o0, o3 = o0;
#pragma unroll
    for (int j = 0; j < 16; j++) {
        float zj = z[j];
        float4 w0 = Ws[j * 4 + 0], w1 = Ws[j * 4 + 1], w2 = Ws[j * 4 + 2], w3 = Ws[j * 4 + 3];
        o0.x += zj * w0.x; o0.y += zj * w0.y; o0.z += zj * w0.z; o0.w += zj * w0.w;
        o1.x += zj * w1.x; o1.y += zj * w1.y; o1.z += zj * w1.z; o1.w += zj * w1.w;
        o2.x += zj * w2.x; o2.y += zj * w2.y; o2.z += zj * w2.z; o2.w += zj * w2.w;
        o3.x += zj * w3.x; o3.y += zj * w3.y; o3.z += zj * w3.z; o3.w += zj * w3.w;
    }
    float s = g_dis[i], sl = s * s;
    g_hB[i * 4 + 0] = o0; g_hB[i * 4 + 1] = o1; g_hB[i * 4 + 2] = o2; g_hB[i * 4 + 3] = o3;
    g_aggB[i * 4 + 0] = make_float4(o0.x*sl, o0.y*sl, o0.z*sl, o0.w*sl);
    g_aggB[i * 4 + 1] = make_float4(o1.x*sl, o1.y*sl, o1.z*sl, o1.w*sl);
    g_aggB[i * 4 + 2] = make_float4(o2.x*sl, o2.y*sl, o2.z*sl, o2.w*sl);
    g_aggB[i * 4 + 3] = make_float4(o3.x*sl, o3.y*sl, o3.z*sl, o3.w*sl);
}

// ---------------- edge pass 2: quad-cooperative, reuses cached norm ----------------
__global__ void edge_pass_b(int e) {
    int t = blockIdx.x * 256 + threadIdx.x;
    int edge = t >> 2, q = t & 3;
    if (edge >= e) return;
    int2 ed = g_edges[edge];
    float nrm = g_norm[edge];
    float4 v = g_hB[ed.x * 4 + q];
    v.x *= nrm; v.y *= nrm; v.z *= nrm; v.w *= nrm;
    red_add_v4(&g_aggB[ed.y * 4 + q], v);
}

// ---------------- layer 3 transform ----------------
__global__ void transform_last(const float* __restrict__ bias, const float* __restrict__ W3, int n) {
    __shared__ float Ws[32];   // 16x2
    __shared__ float bs[16];
    int tid = threadIdx.x;
    if (tid < 32) Ws[tid] = W3[tid];
    if (tid < 16) bs[tid] = bias[tid];
    __syncthreads();
    int i = blockIdx.x * 256 + tid;
    if (i >= n) return;

    float z[16];
#pragma unroll
    for (int q = 0; q < 4; q++) {
        float4 v = g_aggB[i * 4 + q];
        z[q * 4 + 0] = fmaxf(v.x + bs[q * 4 + 0], 0.f);
        z[q * 4 + 1] = fmaxf(v.y + bs[q * 4 + 1], 0.f);
        z[q * 4 + 2] = fmaxf(v.z + bs[q * 4 + 2], 0.f);
        z[q * 4 + 3] = fmaxf(v.w + bs[q * 4 + 3], 0.f);
    }
    float o0 = 0.f, o1 = 0.f;
#pragma unroll
    for (int j = 0; j < 16; j++) {
        o0 += z[j] * Ws[j * 2 + 0];
        o1 += z[j] * Ws[j * 2 + 1];
    }
    float s = g_dis[i], sl = s * s;
    g_h3[i]   = make_float2(o0, o1);
    g_agg3[i] = make_float2(o0 * sl, o1 * sl);
}

// ---------------- edge pass 3 (2-wide) ----------------
__global__ void edge_pass_c(int e) {
    int i = blockIdx.x * 256 + threadIdx.x;
    if (i >= e) return;
    int2 ed = g_edges[i];
    float nrm = g_norm[i];
    float2 v = g_h3[ed.x];
    red_add_v2(&g_agg3[ed.y], make_float2(v.x * nrm, v.y * nrm));
}

// ---------------- final: log_softmax(agg3 + b3) ----------------
__global__ void logsoftmax_out(const float* __restrict__ b3, float* __restrict__ out, int n) {
    int i = blockIdx.x * 256 + threadIdx.x;
    if (i >= n) return;
    float2 a = g_agg3[i];
    float a0 = a.x + b3[0];
    float a1 = a.y + b3[1];
    float m  = fmaxf(a0, a1);
    float lse = m + logf(expf(a0 - m) + expf(a1 - m));
    out[i * 2 + 0] = a0 - lse;
    out[i * 2 + 1] = a1 - lse;
}

// ---------------- launch ----------------
extern "C" void kernel_launch(void* const* d_in, const int* in_sizes, int n_in,
                              void* d_out, int out_size) {
    const float* x  = (const float*)d_in[0];
    const int*   ei = (const int*)d_in[1];     // int32 node ids (2 x E)
    const float* W1 = (const float*)d_in[2];
    const float* b1 = (const float*)d_in[3];
    const float* W2 = (const float*)d_in[4];
    const float* b2 = (const float*)d_in[5];
    const float* W3 = (const float*)d_in[6];
    const float* b3 = (const float*)d_in[7];
    float* out = (float*)d_out;

    int n = in_sizes[0] / 128;   // 100000
    int e = in_sizes[1] / 2;     // 3200000

    int nb  = (n + 255) / 256;
    int ebk = (e + 255) / 256;
    int eqk = (4 * e + 255) / 256;   // quad-cooperative edge grids

    zero_deg<<<nb, 256>>>(n);
    prep_edges<<<ebk, 256>>>(ei, e);
    compute_dis<<<nb, 256>>>(n);

    gemm_in<<<nb, 256>>>((const float4*)x, (const float4*)W1, n);
    edge_pass_a<<<eqk, 256>>>(e);

    transform_mid<<<nb, 256>>>(b1, (const float4*)W2, n);
    edge_pass_b<<<eqk, 256>>>(e);

    transform_last<<<nb, 256>>>(b2, W3, n);
    edge_pass_c<<<ebk, 256>>>(e);

    logsoftmax_out<<<nb, 256>>>(b3, out, n);
}

// round 5
// speedup vs baseline: 1.6938x; 1.0721x over previous
#include <cuda_runtime.h>

#define NN 100000
#define EE 3200000

// ---------------- persistent device scratch ----------------
__device__ int    g_deg[NN];
__device__ int    g_fill[NN];
__device__ int    g_rowstart[NN + 1];
__device__ int    g_bsum[512];
__device__ int    g_csr[EE];
__device__ float  g_dis[NN];
__device__ float4 g_hA[NN * 4];    // layer-1 h~ = (x@W1)*dis  (16 f32/node)
__device__ float4 g_aggA[NN * 4];
__device__ float4 g_hB[NN * 4];    // layer-2 h~
__device__ float4 g_aggB[NN * 4];
__device__ float2 g_h3[NN];        // layer-3 h~ (2 f32/node)

// ---------------- CSR build ----------------
__global__ void zero_deg(int n) {
    int i = blockIdx.x * 256 + threadIdx.x;
    if (i < n) g_deg[i] = 0;
}

__global__ void count_deg(const int* __restrict__ ei, int e) {
    int i = blockIdx.x * 256 + threadIdx.x;
    if (i >= e) return;
    atomicAdd(&g_deg[ei[e + i]], 1);
}

__global__ void scan_block_totals(int n) {
    __shared__ int red[256];
    int tid = threadIdx.x;
    int i = blockIdx.x * 256 + tid;
    red[tid] = (i < n) ? g_deg[i] : 0;
    __syncthreads();
    for (int s = 128; s; s >>= 1) {
        if (tid < s) red[tid] += red[tid + s];
        __syncthreads();
    }
    if (tid == 0) g_bsum[blockIdx.x] = red[0];
}

__global__ void scan_bsums(int nb) {
    __shared__ int sh[512];
    int tid = threadIdx.x;
    int v = (tid < nb) ? g_bsum[tid] : 0;
    sh[tid] = v;
    __syncthreads();
    for (int off = 1; off < 512; off <<= 1) {
        int t = (tid >= off) ? sh[tid - off] : 0;
        __syncthreads();
        sh[tid] += t;
        __syncthreads();
    }
    g_bsum[tid] = sh[tid] - v;   // exclusive offsets
}

__global__ void scan_final(int n) {
    __shared__ int sh[256];
    int tid = threadIdx.x;
    int i = blockIdx.x * 256 + tid;
    int v = (i < n) ? g_deg[i] : 0;
    sh[tid] = v;
    __syncthreads();
    for (int off = 1; off < 256; off <<= 1) {
        int t = (tid >= off) ? sh[tid - off] : 0;
        __syncthreads();
        sh[tid] += t;
        __syncthreads();
    }
    int excl = sh[tid] - v + g_bsum[blockIdx.x];
    if (i < n) {
        g_rowstart[i] = excl;
        g_fill[i] = 0;
        g_dis[i] = rsqrtf((float)(v + 1));   // +1 self-loop
        if (i == n - 1) g_rowstart[n] = excl + v;
    }
}

__global__ void fill_csr(const int* __restrict__ ei, int e) {
    int i = blockIdx.x * 256 + threadIdx.x;
    if (i >= e) return;
    int s = ei[i];
    int d = ei[e + i];
    int pos = g_rowstart[d] + atomicAdd(&g_fill[d], 1);
    g_csr[pos] = s;
}

// ---------------- layer 1: h~A = (x @ W1) * dis ----------------
__global__ void gemm_in(const float4* __restrict__ x4, const float4* __restrict__ W1v, int n) {
    __shared__ float4 wt[512];   // W1 [128][16] row-major as float4
    int tid = threadIdx.x;
    for (int idx = tid; idx < 512; idx += 256) wt[idx] = W1v[idx];
    __syncthreads();

    int node = blockIdx.x * 256 + tid;
    if (node >= n) return;

    float acc[16];
#pragma unroll
    for (int j = 0; j < 16; j++) acc[j] = 0.f;

    const float4* xr = x4 + (size_t)node * 32;
#pragma unroll 8
    for (int kk = 0; kk < 32; kk++) {
        float4 xv = __ldg(&xr[kk]);
        int kb = kk * 16;
#pragma unroll
        for (int j = 0; j < 4; j++) {
            float xs_ = (j == 0) ? xv.x : (j == 1) ? xv.y : (j == 2) ? xv.z : xv.w;
            float4 w0 = wt[kb + j * 4 + 0];
            float4 w1 = wt[kb + j * 4 + 1];
            float4 w2 = wt[kb + j * 4 + 2];
            float4 w3 = wt[kb + j * 4 + 3];
            acc[0]  += xs_ * w0.x; acc[1]  += xs_ * w0.y; acc[2]  += xs_ * w0.z; acc[3]  += xs_ * w0.w;
            acc[4]  += xs_ * w1.x; acc[5]  += xs_ * w1.y; acc[6]  += xs_ * w1.z; acc[7]  += xs_ * w1.w;
            acc[8]  += xs_ * w2.x; acc[9]  += xs_ * w2.y; acc[10] += xs_ * w2.z; acc[11] += xs_ * w2.w;
            acc[12] += xs_ * w3.x; acc[13] += xs_ * w3.y; acc[14] += xs_ * w3.z; acc[15] += xs_ * w3.w;
        }
    }

    float d = g_dis[node];
#pragma unroll
    for (int q = 0; q < 4; q++)
        g_hA[node * 4 + q] = make_float4(acc[q*4+0]*d, acc[q*4+1]*d, acc[q*4+2]*d, acc[q*4+3]*d);
}

// ---------------- 16-wide gather: agg[i] = dis[i] * (sum h~[src] + h~[i]) ----------------
// One warp per node. which=0: hA->aggA, which=1: hB->aggB.
// NOTE: device globals referenced directly (never passed from host — host-side
// symbol is the ATS-visible host shadow on GB300, silently wrong).
__global__ void gather16(int which, int n) {
    int w = (blockIdx.x * 256 + threadIdx.x) >> 5;
    if (w >= n) return;
    int lane = threadIdx.x & 31;
    int q = lane & 3, sub = lane >> 2;
    int start = g_rowstart[w], end = g_rowstart[w + 1];

    const float4* __restrict__ h = (which == 0) ? g_hA : g_hB;
    float4* __restrict__ agg     = (which == 0) ? g_aggA : g_aggB;

    float4 acc = make_float4(0.f, 0.f, 0.f, 0.f);
    for (int p = start + sub; p < end; p += 8) {
        int src = __ldg(&g_csr[p]);
        float4 v = __ldg(&h[src * 4 + q]);
        acc.x += v.x; acc.y += v.y; acc.z += v.z; acc.w += v.w;
    }
#pragma unroll
    for (int m = 4; m < 32; m <<= 1) {
        acc.x += __shfl_xor_sync(0xffffffffu, acc.x, m);
        acc.y += __shfl_xor_sync(0xffffffffu, acc.y, m);
        acc.z += __shfl_xor_sync(0xffffffffu, acc.z, m);
        acc.w += __shfl_xor_sync(0xffffffffu, acc.w, m);
    }
    if (sub == 0) {
        float4 hv = __ldg(&h[w * 4 + q]);   // self-loop
        float d = g_dis[w];
        agg[w * 4 + q] = make_float4((acc.x + hv.x) * d, (acc.y + hv.y) * d,
                                     (acc.z + hv.z) * d, (acc.w + hv.w) * d);
    }
}

// ---------------- layer 2: z = relu(aggA + b1); h~B = (z @ W2) * dis ----------------
__global__ void transform_mid(const float* __restrict__ bias, const float4* __restrict__ W, int n) {
    __shared__ float4 Ws[64];
    __shared__ float  bs[16];
    int tid = threadIdx.x;
    if (tid < 64) Ws[tid] = W[tid];
    if (tid < 16) bs[tid] = bias[tid];
    __syncthreads();
    int i = blockIdx.x * 256 + tid;
    if (i >= n) return;

    float z[16];
#pragma unroll
    for (int q = 0; q < 4; q++) {
        float4 v = g_aggA[i * 4 + q];
        z[q*4+0] = fmaxf(v.x + bs[q*4+0], 0.f);
        z[q*4+1] = fmaxf(v.y + bs[q*4+1], 0.f);
        z[q*4+2] = fmaxf(v.z + bs[q*4+2], 0.f);
        z[q*4+3] = fmaxf(v.w + bs[q*4+3], 0.f);
    }
    float4 o0 = make_float4(0.f,0.f,0.f,0.f), o1 = o0, o2 = o0, o3 = o0;
#pragma unroll
    for (int j = 0; j < 16; j++) {
        float zj = z[j];
        float4 w0 = Ws[j*4+0], w1 = Ws[j*4+1], w2 = Ws[j*4+2], w3 = Ws[j*4+3];
        o0.x += zj*w0.x; o0.y += zj*w0.y; o0.z += zj*w0.z; o0.w += zj*w0.w;
        o1.x += zj*w1.x; o1.y += zj*w1.y; o1.z += zj*w1.z; o1.w += zj*w1.w;
        o2.x += zj*w2.x; o2.y += zj*w2.y; o2.z += zj*w2.z; o2.w += zj*w2.w;
        o3.x += zj*w3.x; o3.y += zj*w3.y; o3.z += zj*w3.z; o3.w += zj*w3.w;
    }
    float d = g_dis[i];
    g_hB[i*4+0] = make_float4(o0.x*d, o0.y*d, o0.z*d, o0.w*d);
    g_hB[i*4+1] = make_float4(o1.x*d, o1.y*d, o1.z*d, o1.w*d);
    g_hB[i*4+2] = make_float4(o2.x*d, o2.y*d, o2.z*d, o2.w*d);
    g_hB[i*4+3] = make_float4(o3.x*d, o3.y*d, o3.z*d, o3.w*d);
}

// ---------------- layer 3: z = relu(aggB + b2); h~3 = (z @ W3) * dis ----------------
__global__ void transform_last(const float* __restrict__ bias, const float* __restrict__ W3, int n) {
    __shared__ float Ws[32];
    __shared__ float bs[16];
    int tid = threadIdx.x;
    if (tid < 32) Ws[tid] = W3[tid];
    if (tid < 16) bs[tid] = bias[tid];
    __syncthreads();
    int i = blockIdx.x * 256 + tid;
    if (i >= n) return;

    float z[16];
#pragma unroll
    for (int q = 0; q < 4; q++) {
        float4 v = g_aggB[i * 4 + q];
        z[q*4+0] = fmaxf(v.x + bs[q*4+0], 0.f);
        z[q*4+1] = fmaxf(v.y + bs[q*4+1], 0.f);
        z[q*4+2] = fmaxf(v.z + bs[q*4+2], 0.f);
        z[q*4+3] = fmaxf(v.w + bs[q*4+3], 0.f);
    }
    float o0 = 0.f, o1 = 0.f;
#pragma unroll
    for (int j = 0; j < 16; j++) {
        o0 += z[j] * Ws[j*2+0];
        o1 += z[j] * Ws[j*2+1];
    }
    float d = g_dis[i];
    g_h3[i] = make_float2(o0 * d, o1 * d);
}

// ---------------- 2-wide gather fused with log_softmax ----------------
__global__ void gather2_out(const float* __restrict__ b3, float* __restrict__ out, int n) {
    int w = (blockIdx.x * 256 + threadIdx.x) >> 5;
    if (w >= n) return;
    int lane = threadIdx.x & 31;
    int start = g_rowstart[w], end = g_rowstart[w + 1];

    float2 acc = make_float2(0.f, 0.f);
    for (int p = start + lane; p < end; p += 32) {
        int src = __ldg(&g_csr[p]);
        float2 v = __ldg(&g_h3[src]);
        acc.x += v.x; acc.y += v.y;
    }
#pragma unroll
    for (int m = 1; m < 32; m <<= 1) {
        acc.x += __shfl_xor_sync(0xffffffffu, acc.x, m);
        acc.y += __shfl_xor_sync(0xffffffffu, acc.y, m);
    }
    if (lane == 0) {
        float2 hv = g_h3[w];
        float d = g_dis[w];
        float a0 = (acc.x + hv.x) * d + b3[0];
        float a1 = (acc.y + hv.y) * d + b3[1];
        float m0 = fmaxf(a0, a1);
        float lse = m0 + logf(expf(a0 - m0) + expf(a1 - m0));
        out[w * 2 + 0] = a0 - lse;
        out[w * 2 + 1] = a1 - lse;
    }
}

// ---------------- launch ----------------
extern "C" void kernel_launch(void* const* d_in, const int* in_sizes, int n_in,
                              void* d_out, int out_size) {
    const float* x  = (const float*)d_in[0];
    const int*   ei = (const int*)d_in[1];
    const float* W1 = (const float*)d_in[2];
    const float* b1 = (const float*)d_in[3];
    const float* W2 = (const float*)d_in[4];
    const float* b2 = (const float*)d_in[5];
    const float* W3 = (const float*)d_in[6];
    const float* b3 = (const float*)d_in[7];
    float* out = (float*)d_out;

    int n = in_sizes[0] / 128;   // 100000
    int e = in_sizes[1] / 2;     // 3200000

    int nb  = (n + 255) / 256;       // 391
    int ebk = (e + 255) / 256;
    int wgb = (n * 32 + 255) / 256;  // warp-per-node grids

    zero_deg<<<nb, 256>>>(n);
    count_deg<<<ebk, 256>>>(ei, e);
    scan_block_totals<<<nb, 256>>>(n);
    scan_bsums<<<1, 512>>>(nb);
    scan_final<<<nb, 256>>>(n);
    fill_csr<<<ebk, 256>>>(ei, e);

    gemm_in<<<nb, 256>>>((const float4*)x, (const float4*)W1, n);
    gather16<<<wgb, 256>>>(0, n);

    transform_mid<<<nb, 256>>>(b1, (const float4*)W2, n);
    gather16<<<wgb, 256>>>(1, n);

    transform_last<<<nb, 256>>>(b2, W3, n);
    gather2_out<<<wgb, 256>>>(b3, out, n);
}

// round 6
// speedup vs baseline: 1.7260x; 1.0190x over previous
#include <cuda_runtime.h>

#define NN 100000
#define EE 3200000

// ---------------- persistent device scratch ----------------
__device__ int    g_deg[NN];
__device__ int    g_fill[NN];
__device__ int    g_rowstart[NN + 1];
__device__ int    g_bsum[512];
__device__ int    g_csr[EE];
__device__ float  g_dis[NN];
__device__ float4 g_hA[NN * 4];    // layer-1 h~ = (x@W1)*dis  (16 f32/node)
__device__ float4 g_aggA[NN * 4];
__device__ float4 g_hB[NN * 4];    // layer-2 h~
__device__ float4 g_aggB[NN * 4];
__device__ float2 g_h3[NN];        // layer-3 h~ (2 f32/node)

// ---------------- CSR build ----------------
__global__ void count_deg(const int* __restrict__ ei, int e) {
    int i = blockIdx.x * 256 + threadIdx.x;
    if (i >= e) return;
    atomicAdd(&g_deg[ei[e + i]], 1);
}

__global__ void scan_block_totals(int n) {
    __shared__ int red[256];
    int tid = threadIdx.x;
    int i = blockIdx.x * 256 + tid;
    red[tid] = (i < n) ? g_deg[i] : 0;
    __syncthreads();
    for (int s = 128; s; s >>= 1) {
        if (tid < s) red[tid] += red[tid + s];
        __syncthreads();
    }
    if (tid == 0) g_bsum[blockIdx.x] = red[0];
}

__global__ void scan_bsums(int nb) {
    __shared__ int sh[512];
    int tid = threadIdx.x;
    int v = (tid < nb) ? g_bsum[tid] : 0;
    sh[tid] = v;
    __syncthreads();
    for (int off = 1; off < 512; off <<= 1) {
        int t = (tid >= off) ? sh[tid - off] : 0;
        __syncthreads();
        sh[tid] += t;
        __syncthreads();
    }
    g_bsum[tid] = sh[tid] - v;   // exclusive offsets
}

__global__ void scan_final(int n) {
    __shared__ int sh[256];
    int tid = threadIdx.x;
    int i = blockIdx.x * 256 + tid;
    int v = (i < n) ? g_deg[i] : 0;
    sh[tid] = v;
    __syncthreads();
    for (int off = 1; off < 256; off <<= 1) {
        int t = (tid >= off) ? sh[tid - off] : 0;
        __syncthreads();
        sh[tid] += t;
        __syncthreads();
    }
    int excl = sh[tid] - v + g_bsum[blockIdx.x];
    if (i < n) {
        g_rowstart[i] = excl;
        g_fill[i] = 0;
        g_dis[i] = rsqrtf((float)(v + 1));   // +1 self-loop
        if (i == n - 1) g_rowstart[n] = excl + v;
    }
}

__global__ void fill_csr(const int* __restrict__ ei, int e) {
    int i = blockIdx.x * 256 + threadIdx.x;
    if (i >= e) return;
    int s = ei[i];
    int d = ei[e + i];
    int pos = g_rowstart[d] + atomicAdd(&g_fill[d], 1);
    g_csr[pos] = s;
}

// ---------------- layer 1: h~A = (x @ W1) * dis  (MLP-16 batched loads) ----------------
__global__ void gemm_in(const float4* __restrict__ x4, const float4* __restrict__ W1v, int n) {
    __shared__ float4 wt[512];   // W1 [128][16] row-major as float4
    int tid = threadIdx.x;
    for (int idx = tid; idx < 512; idx += 256) wt[idx] = W1v[idx];
    __syncthreads();

    int node = blockIdx.x * 256 + tid;
    if (node >= n) return;

    float acc[16];
#pragma unroll
    for (int j = 0; j < 16; j++) acc[j] = 0.f;

    const float4* xr = x4 + (size_t)node * 32;
    float4 xv[16];

#pragma unroll
    for (int half = 0; half < 2; half++) {
        int kb0 = half * 16;
#pragma unroll
        for (int i = 0; i < 16; i++) xv[i] = __ldg(&xr[kb0 + i]);   // 16 loads in flight
#pragma unroll
        for (int i = 0; i < 16; i++) {
            float4 v = xv[i];
            int kb = (kb0 + i) * 16;
#pragma unroll
            for (int j = 0; j < 4; j++) {
                float xs_ = (j == 0) ? v.x : (j == 1) ? v.y : (j == 2) ? v.z : v.w;
                float4 w0 = wt[kb + j * 4 + 0];
                float4 w1 = wt[kb + j * 4 + 1];
                float4 w2 = wt[kb + j * 4 + 2];
                float4 w3 = wt[kb + j * 4 + 3];
                acc[0]  += xs_ * w0.x; acc[1]  += xs_ * w0.y; acc[2]  += xs_ * w0.z; acc[3]  += xs_ * w0.w;
                acc[4]  += xs_ * w1.x; acc[5]  += xs_ * w1.y; acc[6]  += xs_ * w1.z; acc[7]  += xs_ * w1.w;
                acc[8]  += xs_ * w2.x; acc[9]  += xs_ * w2.y; acc[10] += xs_ * w2.z; acc[11] += xs_ * w2.w;
                acc[12] += xs_ * w3.x; acc[13] += xs_ * w3.y; acc[14] += xs_ * w3.z; acc[15] += xs_ * w3.w;
            }
        }
    }

    float d = g_dis[node];
#pragma unroll
    for (int q = 0; q < 4; q++)
        g_hA[node * 4 + q] = make_float4(acc[q*4+0]*d, acc[q*4+1]*d, acc[q*4+2]*d, acc[q*4+3]*d);
}

// ---------------- 16-wide gather v2: coalesced csr + shfl distribute + MLP-4 ----------------
// One warp per node. Lane layout: q = lane&3 owns feature quad q, sub = lane>>2.
// Per 32-edge macro-chunk: lane loads csr[start+lane] (coalesced), shfl gives each
// sub 4 src ids; each lane issues 4 independent 16B gathers.
__global__ void gather16(int which, int n) {
    int w = (blockIdx.x * 256 + threadIdx.x) >> 5;
    if (w >= n) return;
    int lane = threadIdx.x & 31;
    int q = lane & 3, sub = lane >> 2;
    int start = g_rowstart[w], deg = g_rowstart[w + 1] - start;

    const float4* __restrict__ h = (which == 0) ? g_hA : g_hB;
    float4* __restrict__ agg     = (which == 0) ? g_aggA : g_aggB;

    float4 acc = make_float4(0.f, 0.f, 0.f, 0.f);
    for (int base = 0; base < deg; base += 32) {
        int p = base + lane;
        int idx = (p < deg) ? __ldg(&g_csr[start + p]) : 0;
        int s0 = __shfl_sync(0xffffffffu, idx, sub);
        int s1 = __shfl_sync(0xffffffffu, idx, sub + 8);
        int s2 = __shfl_sync(0xffffffffu, idx, sub + 16);
        int s3 = __shfl_sync(0xffffffffu, idx, sub + 24);
        bool v0 = (base + sub)      < deg;
        bool v1 = (base + sub + 8)  < deg;
        bool v2 = (base + sub + 16) < deg;
        bool v3 = (base + sub + 24) < deg;
        float4 a = v0 ? __ldg(&h[s0 * 4 + q]) : make_float4(0.f,0.f,0.f,0.f);
        float4 b = v1 ? __ldg(&h[s1 * 4 + q]) : make_float4(0.f,0.f,0.f,0.f);
        float4 c = v2 ? __ldg(&h[s2 * 4 + q]) : make_float4(0.f,0.f,0.f,0.f);
        float4 d = v3 ? __ldg(&h[s3 * 4 + q]) : make_float4(0.f,0.f,0.f,0.f);
        acc.x += a.x + b.x + c.x + d.x;
        acc.y += a.y + b.y + c.y + d.y;
        acc.z += a.z + b.z + c.z + d.z;
        acc.w += a.w + b.w + c.w + d.w;
    }
#pragma unroll
    for (int m = 4; m < 32; m <<= 1) {
        acc.x += __shfl_xor_sync(0xffffffffu, acc.x, m);
        acc.y += __shfl_xor_sync(0xffffffffu, acc.y, m);
        acc.z += __shfl_xor_sync(0xffffffffu, acc.z, m);
        acc.w += __shfl_xor_sync(0xffffffffu, acc.w, m);
    }
    if (sub == 0) {
        float4 hv = __ldg(&h[w * 4 + q]);   // self-loop
        float d = g_dis[w];
        agg[w * 4 + q] = make_float4((acc.x + hv.x) * d, (acc.y + hv.y) * d,
                                     (acc.z + hv.z) * d, (acc.w + hv.w) * d);
    }
}

// ---------------- layer 2: z = relu(aggA + b1); h~B = (z @ W2) * dis ----------------
__global__ void transform_mid(const float* __restrict__ bias, const float4* __restrict__ W, int n) {
    __shared__ float4 Ws[64];
    __shared__ float  bs[16];
    int tid = threadIdx.x;
    if (tid < 64) Ws[tid] = W[tid];
    if (tid < 16) bs[tid] = bias[tid];
    __syncthreads();
    int i = blockIdx.x * 256 + tid;
    if (i >= n) return;

    float z[16];
#pragma unroll
    for (int q = 0; q < 4; q++) {
        float4 v = g_aggA[i * 4 + q];
        z[q*4+0] = fmaxf(v.x + bs[q*4+0], 0.f);
        z[q*4+1] = fmaxf(v.y + bs[q*4+1], 0.f);
        z[q*4+2] = fmaxf(v.z + bs[q*4+2], 0.f);
        z[q*4+3] = fmaxf(v.w + bs[q*4+3], 0.f);
    }
    float4 o0 = make_float4(0.f,0.f,0.f,0.f), o1 = o0, o2 = o0, o3 = o0;
#pragma unroll
    for (int j = 0; j < 16; j++) {
        float zj = z[j];
        float4 w0 = Ws[j*4+0], w1 = Ws[j*4+1], w2 = Ws[j*4+2], w3 = Ws[j*4+3];
        o0.x += zj*w0.x; o0.y += zj*w0.y; o0.z += zj*w0.z; o0.w += zj*w0.w;
        o1.x += zj*w1.x; o1.y += zj*w1.y; o1.z += zj*w1.z; o1.w += zj*w1.w;
        o2.x += zj*w2.x; o2.y += zj*w2.y; o2.z += zj*w2.z; o2.w += zj*w2.w;
        o3.x += zj*w3.x; o3.y += zj*w3.y; o3.z += zj*w3.z; o3.w += zj*w3.w;
    }
    float d = g_dis[i];
    g_hB[i*4+0] = make_float4(o0.x*d, o0.y*d, o0.z*d, o0.w*d);
    g_hB[i*4+1] = make_float4(o1.x*d, o1.y*d, o1.z*d, o1.w*d);
    g_hB[i*4+2] = make_float4(o2.x*d, o2.y*d, o2.z*d, o2.w*d);
    g_hB[i*4+3] = make_float4(o3.x*d, o3.y*d, o3.z*d, o3.w*d);
}

// ---------------- layer 3: z = relu(aggB + b2); h~3 = (z @ W3) * dis ----------------
__global__ void transform_last(const float* __restrict__ bias, const float* __restrict__ W3, int n) {
    __shared__ float Ws[32];
    __shared__ float bs[16];
    int tid = threadIdx.x;
    if (tid < 32) Ws[tid] = W3[tid];
    if (tid < 16) bs[tid] = bias[tid];
    __syncthreads();
    int i = blockIdx.x * 256 + tid;
    if (i >= n) return;

    float z[16];
#pragma unroll
    for (int q = 0; q < 4; q++) {
        float4 v = g_aggB[i * 4 + q];
        z[q*4+0] = fmaxf(v.x + bs[q*4+0], 0.f);
        z[q*4+1] = fmaxf(v.y + bs[q*4+1], 0.f);
        z[q*4+2] = fmaxf(v.z + bs[q*4+2], 0.f);
        z[q*4+3] = fmaxf(v.w + bs[q*4+3], 0.f);
    }
    float o0 = 0.f, o1 = 0.f;
#pragma unroll
    for (int j = 0; j < 16; j++) {
        o0 += z[j] * Ws[j*2+0];
        o1 += z[j] * Ws[j*2+1];
    }
    float d = g_dis[i];
    g_h3[i] = make_float2(o0 * d, o1 * d);
}

// ---------------- 2-wide gather fused with log_softmax ----------------
__global__ void gather2_out(const float* __restrict__ b3, float* __restrict__ out, int n) {
    int w = (blockIdx.x * 256 + threadIdx.x) >> 5;
    if (w >= n) return;
    int lane = threadIdx.x & 31;
    int start = g_rowstart[w], end = g_rowstart[w + 1];

    float2 acc = make_float2(0.f, 0.f);
    for (int p = start + lane; p < end; p += 32) {
        int src = __ldg(&g_csr[p]);
        float2 v = __ldg(&g_h3[src]);
        acc.x += v.x; acc.y += v.y;
    }
#pragma unroll
    for (int m = 1; m < 32; m <<= 1) {
        acc.x += __shfl_xor_sync(0xffffffffu, acc.x, m);
        acc.y += __shfl_xor_sync(0xffffffffu, acc.y, m);
    }
    if (lane == 0) {
        float2 hv = g_h3[w];
        float d = g_dis[w];
        float a0 = (acc.x + hv.x) * d + b3[0];
        float a1 = (acc.y + hv.y) * d + b3[1];
        float m0 = fmaxf(a0, a1);
        float lse = m0 + logf(expf(a0 - m0) + expf(a1 - m0));
        out[w * 2 + 0] = a0 - lse;
        out[w * 2 + 1] = a1 - lse;
    }
}

// ---------------- launch ----------------
extern "C" void kernel_launch(void* const* d_in, const int* in_sizes, int n_in,
                              void* d_out, int out_size) {
    const float* x  = (const float*)d_in[0];
    const int*   ei = (const int*)d_in[1];
    const float* W1 = (const float*)d_in[2];
    const float* b1 = (const float*)d_in[3];
    const float* W2 = (const float*)d_in[4];
    const float* b2 = (const float*)d_in[5];
    const float* W3 = (const float*)d_in[6];
    const float* b3 = (const float*)d_in[7];
    float* out = (float*)d_out;

    int n = in_sizes[0] / 128;   // 100000
    int e = in_sizes[1] / 2;     // 3200000

    int nb  = (n + 255) / 256;       // 391
    int ebk = (e + 255) / 256;
    int wgb = (n * 32 + 255) / 256;  // warp-per-node grids

    void* degp = nullptr;
    cudaGetSymbolAddress(&degp, g_deg);
    cudaMemsetAsync(degp, 0, (size_t)n * sizeof(int));

    count_deg<<<ebk, 256>>>(ei, e);
    scan_block_totals<<<nb, 256>>>(n);
    scan_bsums<<<1, 512>>>(nb);
    scan_final<<<nb, 256>>>(n);
    fill_csr<<<ebk, 256>>>(ei, e);

    gemm_in<<<nb, 256>>>((const float4*)x, (const float4*)W1, n);
    gather16<<<wgb, 256>>>(0, n);

    transform_mid<<<nb, 256>>>(b1, (const float4*)W2, n);
    gather16<<<wgb, 256>>>(1, n);

    transform_last<<<nb, 256>>>(b2, W3, n);
    gather2_out<<<wgb, 256>>>(b3, out, n);
}